// round 16
// baseline (speedup 1.0000x reference)
#include <cuda_runtime.h>
#include <cuda_bf16.h>
#include <math.h>
#include <stdint.h>

// Problem constants
#define Vv 50000
#define Ee 256
#define HD 512
#define Hh 256
#define Bb 64
#define Tt 512
#define Kk 16
#define G4H 1024
#define START_IDX 14
#define STOP_IDX 15
#define NEG (-10000.0f)

// ---------------- device scratch ----------------
__device__ __align__(16) float g_Wr2[2 * 1024 * 256];               // [d][col][k], col=j*4+gate
__device__ __align__(16) float g_Gpre[2ull * Tt * Bb * G4H];        // 268 MB
__device__ __align__(16) float g_hs[2ull * Tt * Bb * Hh];           // 67 MB
__device__ float g_feats[(size_t)Tt * Bb * Kk];

// ---------------- f32x2 helpers ----------------
__device__ __forceinline__ void ffma2(unsigned long long& d,
                                      unsigned long long a, unsigned long long b) {
    asm("fma.rn.f32x2 %0, %1, %2, %0;" : "+l"(d) : "l"(a), "l"(b));
}
__device__ __forceinline__ unsigned long long pack2(float x, float y) {
    unsigned long long r;
    asm("mov.b64 %0, {%1, %2};" : "=l"(r) : "f"(x), "f"(y));
    return r;
}
__device__ __forceinline__ float hadd2(unsigned long long v) {
    float lo = __uint_as_float((unsigned)(v & 0xffffffffull));
    float hi = __uint_as_float((unsigned)(v >> 32));
    return lo + hi;
}
__device__ __forceinline__ float fsig(float x) {
    return __fdividef(1.0f, 1.0f + __expf(-x));
}
__device__ __forceinline__ float ftanh(float x) {
    return __fdividef(2.0f, 1.0f + __expf(-2.0f * x)) - 1.0f;
}

// ---------------- cluster mbarrier helpers ----------------
__device__ __forceinline__ uint32_t smem_u32_of(const void* p) {
    uint32_t a;
    asm("{ .reg .u64 t0; cvta.to.shared.u64 t0, %1; cvt.u32.u64 %0, t0; }"
        : "=r"(a) : "l"(p));
    return a;
}
__device__ __forceinline__ void mbar_init(uint32_t mbar, uint32_t cnt) {
    asm volatile("mbarrier.init.shared.b64 [%0], %1;" :: "r"(mbar), "r"(cnt) : "memory");
}
__device__ __forceinline__ void mbar_arrive_expect(uint32_t mbar, uint32_t tx) {
    asm volatile("mbarrier.arrive.expect_tx.shared.b64 _, [%0], %1;"
                 :: "r"(mbar), "r"(tx) : "memory");
}
__device__ __forceinline__ void mbar_wait_cluster(uint32_t mbar, uint32_t parity) {
    asm volatile(
        "{\n\t"
        ".reg .pred P1;\n\t"
        "WAIT_%=:\n\t"
        "mbarrier.try_wait.parity.acquire.cta.shared::cta.b64 P1, [%0], %1, 0x989680;\n\t"
        "@P1 bra.uni DONE_%=;\n\t"
        "bra.uni WAIT_%=;\n\t"
        "DONE_%=:\n\t"
        "}"
        :: "r"(mbar), "r"(parity) : "memory");
}
__device__ __forceinline__ uint32_t mapa_u32(uint32_t addr, uint32_t rank) {
    uint32_t r;
    asm("mapa.shared::cluster.u32 %0, %1, %2;" : "=r"(r) : "r"(addr), "r"(rank));
    return r;
}
__device__ __forceinline__ void st_async_f64(uint32_t daddr, unsigned long long val,
                                             uint32_t mbar) {
    asm volatile(
        "st.async.weak.shared::cluster.mbarrier::complete_tx::bytes.b64 [%0], %1, [%2];"
        :: "r"(daddr), "l"(val), "r"(mbar) : "memory");
}

// ---------------- kernel 0: reorder recurrent weights ----------------
__global__ void prep_whh_kernel(const float* __restrict__ whh_f,
                                const float* __restrict__ whh_b) {
    int idx = blockIdx.x * blockDim.x + threadIdx.x;   // over 2*1024*256
    int k = idx & 255;
    int col = (idx >> 8) & 1023;
    int d = idx >> 18;
    int gate = col & 3;
    int j = col >> 2;
    const float* w = d ? whh_b : whh_f;
    g_Wr2[idx] = w[(gate * 256 + j) * 256 + k];
}

// ---------------- dummy kernel (rotates the sticky ncu capture slot) --------
__global__ void dummy_kernel() {}

// ---------------- kernel 1: embedding gather + input projection SGEMM ----------------
// R16: occupancy-2 retile. Block tile 128m x 128n, BK=8, thread tile 8m x 8n.
// acc2[4][8] u64 (64 reg-slots) + temps ~= 115 regs -> fits 128-reg occ-2 cap.
// A natural layout: LDS.128 yields native (m,m+1) pairs for FFMA2 -> per-output
// k-order identical to the R5 kernel => bit-identical Gpre.
// Per kk per thread: 64 B LDS / 64 MAC = 1.0 B/MAC (~37% of crossbar at floor).
__global__ __launch_bounds__(256, 2) void input_proj_kernel(
    const int*   __restrict__ sentence,
    const float* __restrict__ emb,
    const float* __restrict__ wih_f, const float* __restrict__ bf,
    const float* __restrict__ wih_b, const float* __restrict__ bbias) {
    const int d = blockIdx.z;
    const float* wih = d ? wih_b : wih_f;
    const float* bias = d ? bbias : bf;

    __shared__ __align__(16) float As[2][8][128];    // 8 KB
    __shared__ __align__(16) float Bs[2][8][128];    // 8 KB

    const int tid = threadIdx.x;
    const int tx = tid & 15;          // n-group (8 cols)
    const int ty = tid >> 4;          // m-group (8 rows = 4 m-pairs)
    const int m0 = blockIdx.y * 128;
    const int c0 = blockIdx.x * 128;

    // A loader: row lr = tid&127, k-half = (tid>>7)*4 (one float4 per slab)
    const int lr = tid & 127;
    const int kh = (tid >> 7) * 4;
    const int mA = m0 + lr;
    const int tok = sentence[(mA & 63) * Tt + (mA >> 6)];
    const float* arow = emb + (size_t)tok * Ee + kh;
    // B loader: col lr, same k-half
    const int cB = c0 + lr;
    const int rB = ((cB & 3) << 8) | (cB >> 2);
    const float* brow = wih + (size_t)rB * Ee + kh;

    unsigned long long acc2[4][8];    // 4 m-pairs x 8 n
#pragma unroll
    for (int i = 0; i < 4; i++)
#pragma unroll
        for (int j = 0; j < 8; j++) acc2[i][j] = 0ull;

    // prologue: fill buffer 0
    {
        float4 av = *(const float4*)(arow);
        float4 bv = *(const float4*)(brow);
        float avv[4] = {av.x, av.y, av.z, av.w};
        float bvv[4] = {bv.x, bv.y, bv.z, bv.w};
#pragma unroll
        for (int i = 0; i < 4; i++) {
            As[0][kh + i][lr] = avv[i];
            Bs[0][kh + i][lr] = bvv[i];
        }
    }
    __syncthreads();

    for (int it = 0; it < 32; it++) {
        const int cur = it & 1;
        float4 avn, bvn;
        if (it < 31) {
            avn = *(const float4*)(arow + (it + 1) * 8);
            bvn = *(const float4*)(brow + (it + 1) * 8);
        }
#pragma unroll
        for (int kk = 0; kk < 8; kk++) {
            const ulonglong2* pa = (const ulonglong2*)&As[cur][kk][ty * 8];
            ulonglong2 p0 = pa[0], p1 = pa[1];
            unsigned long long ra[4] = {p0.x, p0.y, p1.x, p1.y};
            const float4* pb = (const float4*)&Bs[cur][kk][tx * 8];
            float4 b0 = pb[0], b1 = pb[1];
            unsigned long long rb2[8];
            rb2[0] = pack2(b0.x, b0.x); rb2[1] = pack2(b0.y, b0.y);
            rb2[2] = pack2(b0.z, b0.z); rb2[3] = pack2(b0.w, b0.w);
            rb2[4] = pack2(b1.x, b1.x); rb2[5] = pack2(b1.y, b1.y);
            rb2[6] = pack2(b1.z, b1.z); rb2[7] = pack2(b1.w, b1.w);
#pragma unroll
            for (int mp = 0; mp < 4; mp++)
#pragma unroll
                for (int n = 0; n < 8; n++) ffma2(acc2[mp][n], ra[mp], rb2[n]);
        }
        if (it < 31) {
            const int nxt = cur ^ 1;
            float avv[4] = {avn.x, avn.y, avn.z, avn.w};
            float bvv[4] = {bvn.x, bvn.y, bvn.z, bvn.w};
#pragma unroll
            for (int i = 0; i < 4; i++) {
                As[nxt][kh + i][lr] = avv[i];
                Bs[nxt][kh + i][lr] = bvv[i];
            }
        }
        __syncthreads();
    }

    float bsv[8];
#pragma unroll
    for (int n = 0; n < 8; n++) {
        int c = c0 + tx * 8 + n;
        bsv[n] = bias[((c & 3) << 8) | (c >> 2)];
    }
#pragma unroll
    for (int mp = 0; mp < 4; mp++) {
        const int me = m0 + ty * 8 + 2 * mp;      // even m
        float oe[8], oo[8];
#pragma unroll
        for (int n = 0; n < 8; n++) {
            unsigned long long v = acc2[mp][n];
            oe[n] = __uint_as_float((unsigned)(v & 0xffffffffull)) + bsv[n];
            oo[n] = __uint_as_float((unsigned)(v >> 32)) + bsv[n];
        }
        {
            int t = me >> 6, b = me & 63;
            float* outp = g_Gpre + (((size_t)d * Tt + t) * Bb + b) * G4H + c0 + tx * 8;
            *(float4*)(outp) = make_float4(oe[0], oe[1], oe[2], oe[3]);
            *(float4*)(outp + 4) = make_float4(oe[4], oe[5], oe[6], oe[7]);
        }
        {
            int mo = me + 1;
            int t = mo >> 6, b = mo & 63;
            float* outp = g_Gpre + (((size_t)d * Tt + t) * Bb + b) * G4H + c0 + tx * 8;
            *(float4*)(outp) = make_float4(oo[0], oo[1], oo[2], oo[3]);
            *(float4*)(outp + 4) = make_float4(oo[4], oo[5], oo[6], oo[7]);
        }
    }
}

// ---------------- kernel 2: LSTM recurrence (R5 layout — proven best) ----------
// 128 CTAs, cluster 8. cid=blk>>3: d=cid>>3, batch group bg=cid&7 (8 batches).
// CTA rank r owns j in [r*32, r*32+32). Thread: jl=t>>3, kq=t&7 (k-split 8-way).
// Weights in registers. h pair-packed (shfl_xor 8) and broadcast via
// st.async.b64 from even-jl threads; per-step sync = tx-counted mbarrier.
// Gpre prefetch stays AFTER the GEMM (hoisting it spills at the 255-reg cap).
__global__ void __cluster_dims__(8, 1, 1) __launch_bounds__(256, 1) lstm_rec_kernel() {
    const int tidx = threadIdx.x;
    const int kq = tidx & 7;
    const int jl = tidx >> 3;
    const int cid = blockIdx.x >> 3;
    const int r = blockIdx.x & 7;
    const int d = cid >> 3;
    const int bg = cid & 7;
    const int b = bg * 8 + kq;
    const int jglob = r * 32 + jl;
    const int col0 = jglob * 4;

    __shared__ __align__(16) float h_sm[2][8][260];
    __shared__ __align__(8) unsigned long long mbars[2];

    // ---- weights into registers ----
    unsigned long long wu[4][16];
    const float* wbase = g_Wr2 + (size_t)d * 1024 * 256;
#pragma unroll
    for (int g = 0; g < 4; g++) {
        const ulonglong2* p = (const ulonglong2*)(wbase + (size_t)(col0 + g) * 256 + kq * 32);
#pragma unroll
        for (int q = 0; q < 8; q++) {
            ulonglong2 v = p[q];
            wu[g][2 * q + 0] = v.x;
            wu[g][2 * q + 1] = v.y;
        }
    }

    // zero step-0 buffer
    for (int i = tidx; i < 8 * 260; i += 256) ((float*)h_sm[0])[i] = 0.0f;
    float c = 0.0f;

    const uint32_t h_base = smem_u32_of(h_sm);
    const uint32_t mb_base = smem_u32_of(mbars);
    const uint32_t dmb = mb_base - h_base;

    if (tidx == 0) {
        mbar_init(mb_base, 1);
        mbar_init(mb_base + 8, 1);
        mbar_arrive_expect(mb_base, 8192);
        mbar_arrive_expect(mb_base + 8, 8192);
    }
    __syncthreads();
    asm volatile("barrier.cluster.arrive.aligned;" ::: "memory");
    asm volatile("barrier.cluster.wait.aligned;" ::: "memory");

    uint32_t ph[8];
#pragma unroll
    for (int rk = 0; rk < 8; rk++) ph[rk] = mapa_u32(h_base, rk);

    // pair store: even-jl thread writes (h_j, h_{j+1}) at float offset kq*260 + jglob
    const uint32_t hoff0 = (uint32_t)((kq * 260 + jglob) * 4);
    const uint32_t hoff1 = (uint32_t)(8 * 260 * 4) + hoff0;
    const bool sender = ((jl & 1) == 0);

    const int t0 = d ? (Tt - 1) : 0;
    const int tstep = d ? -1 : 1;
    const float4* gpre4 = (const float4*)g_Gpre;

    float4 g4 = gpre4[(((size_t)d * Tt + t0) * Bb + b) * 256 + jglob];

    for (int s = 0; s < Tt; s++) {
        const int t = t0 + s * tstep;
        const int cur = s & 1;

        if (s > 0) {
            uint32_t mb = mb_base + (uint32_t)(cur * 8);
            mbar_wait_cluster(mb, ((s - 1) >> 1) & 1);
            if (tidx == 0) mbar_arrive_expect(mb, 8192);   // re-arm for step s+2
        }

        // ---- GEMM: accf[g][slot], row = slot ^ kq ----
        float accf[4][8];
#pragma unroll
        for (int sl = 0; sl < 8; sl++) {
            unsigned long long a2[4] = {0ull, 0ull, 0ull, 0ull};
            const ulonglong2* hp = (const ulonglong2*)&h_sm[cur][sl ^ kq][kq * 32];
#pragma unroll
            for (int i = 0; i < 8; i++) {
                ulonglong2 h4 = hp[i];
                ffma2(a2[0], wu[0][2 * i], h4.x); ffma2(a2[0], wu[0][2 * i + 1], h4.y);
                ffma2(a2[1], wu[1][2 * i], h4.x); ffma2(a2[1], wu[1][2 * i + 1], h4.y);
                ffma2(a2[2], wu[2][2 * i], h4.x); ffma2(a2[2], wu[2][2 * i + 1], h4.y);
                ffma2(a2[3], wu[3][2 * i], h4.x); ffma2(a2[3], wu[3][2 * i + 1], h4.y);
            }
#pragma unroll
            for (int g = 0; g < 4; g++) accf[g][sl] = hadd2(a2[g]);
        }

        // prefetch next step's Gpre
        float4 g4n = g4;
        if (s + 1 < Tt) {
            const int tn = t + tstep;
            g4n = gpre4[(((size_t)d * Tt + tn) * Bb + b) * 256 + jglob];
        }

        // ---- reduce-scatter over kq lanes ----
#pragma unroll
        for (int g = 0; g < 4; g++) {
            accf[g][0] += __shfl_xor_sync(0xffffffffu, accf[g][4], 4);
            accf[g][1] += __shfl_xor_sync(0xffffffffu, accf[g][5], 4);
            accf[g][2] += __shfl_xor_sync(0xffffffffu, accf[g][6], 4);
            accf[g][3] += __shfl_xor_sync(0xffffffffu, accf[g][7], 4);
            accf[g][0] += __shfl_xor_sync(0xffffffffu, accf[g][2], 2);
            accf[g][1] += __shfl_xor_sync(0xffffffffu, accf[g][3], 2);
            accf[g][0] += __shfl_xor_sync(0xffffffffu, accf[g][1], 1);
        }

        // ---- LSTM cell ----
        float a0 = accf[0][0] + g4.x;
        float a1 = accf[1][0] + g4.y;
        float a2v = accf[2][0] + g4.z;
        float a3 = accf[3][0] + g4.w;
        float ig = fsig(a0), fg = fsig(a1), gv = ftanh(a2v), og = fsig(a3);
        c = fg * c + ig * gv;
        float h = og * ftanh(c);

        g_hs[(((size_t)d * Tt + t) * Bb + b) * Hh + jglob] = h;

        // pair h with jl-neighbor (lane ^ 8), even-jl threads send b64
        float hN = __shfl_xor_sync(0xffffffffu, h, 8);
        if (s + 1 < Tt && sender) {
            unsigned long long hv = pack2(h, hN);
            const uint32_t doff = (cur ^ 1) ? hoff1 : hoff0;
            const uint32_t moff = dmb + (uint32_t)((cur ^ 1) * 8);
#pragma unroll
            for (int rk = 0; rk < 8; rk++)
                st_async_f64(ph[rk] + doff, hv, ph[rk] + moff);
        }
        g4 = g4n;
    }
}

// ---------------- kernel 3: emission features ----------------
__global__ __launch_bounds__(256) void feats_kernel(const float* __restrict__ w_out,
                                                    const float* __restrict__ b_out) {
    const int lane = threadIdx.x & 31;
    const int warp = threadIdx.x >> 5;
    const int m = blockIdx.x * 8 + warp;
    const int t = m >> 6, b = m & 63;

    __shared__ float f_sm[8][16];

    float acc[16];
#pragma unroll
    for (int kk = 0; kk < 16; kk++) acc[kk] = 0.0f;

    const float* hf = g_hs + ((size_t)t * Bb + b) * Hh;
    const float* hb = g_hs + ((size_t)Tt * Bb * Hh) + ((size_t)t * Bb + b) * Hh;

#pragma unroll
    for (int i = 0; i < 16; i++) {
        int dd = i * 32 + lane;
        float hv = (dd < Hh) ? hf[dd] : hb[dd - Hh];
#pragma unroll
        for (int kk = 0; kk < 16; kk++) acc[kk] += hv * w_out[kk * HD + dd];
    }
#pragma unroll
    for (int kk = 0; kk < 16; kk++) {
        float s = acc[kk];
        s += __shfl_down_sync(0xffffffffu, s, 16);
        s += __shfl_down_sync(0xffffffffu, s, 8);
        s += __shfl_down_sync(0xffffffffu, s, 4);
        s += __shfl_down_sync(0xffffffffu, s, 2);
        s += __shfl_down_sync(0xffffffffu, s, 1);
        if (lane == 0) f_sm[warp][kk] = s;
    }
    __syncwarp();
    if (lane < 16)
        g_feats[((size_t)t * Bb + b) * Kk + lane] = f_sm[warp][lane] + b_out[lane];
}

// ---------------- kernel 4: Viterbi forward + backtrace (tree max/argmax) ------
__global__ __launch_bounds__(32) void viterbi_kernel(const float* __restrict__ trans,
                                                     float* __restrict__ out) {
    const int b = blockIdx.x;
    const int lane = threadIdx.x;

    __shared__ unsigned char bp_sm[Tt][16];

    float trans_r[16];
#pragma unroll
    for (int p = 0; p < 16; p++)
        trans_r[p] = (lane < 16) ? trans[lane * 16 + p] : 0.0f;

    float fv = (lane == START_IDX) ? 0.0f : NEG;
    if (lane >= 16) fv = NEG;

    float feat_n = (lane < 16) ? g_feats[((size_t)0 * Bb + b) * Kk + lane] : 0.0f;

    for (int t = 0; t < Tt; t++) {
        float feat = feat_n;
        if (t + 1 < Tt)
            feat_n = (lane < 16) ? g_feats[((size_t)(t + 1) * Bb + b) * Kk + lane] : 0.0f;

        float v[16];
#pragma unroll
        for (int p = 0; p < 16; p++)
            v[p] = __shfl_sync(0xffffffffu, fv, p) + trans_r[p];

        float mv[8]; int mi[8];
#pragma unroll
        for (int p = 0; p < 8; p++) {
            bool ge = v[2 * p] >= v[2 * p + 1];
            mv[p] = ge ? v[2 * p] : v[2 * p + 1];
            mi[p] = ge ? (2 * p) : (2 * p + 1);
        }
#pragma unroll
        for (int p = 0; p < 4; p++) {
            bool ge = mv[2 * p] >= mv[2 * p + 1];
            mv[p] = ge ? mv[2 * p] : mv[2 * p + 1];
            mi[p] = ge ? mi[2 * p] : mi[2 * p + 1];
        }
#pragma unroll
        for (int p = 0; p < 2; p++) {
            bool ge = mv[2 * p] >= mv[2 * p + 1];
            mv[p] = ge ? mv[2 * p] : mv[2 * p + 1];
            mi[p] = ge ? mi[2 * p] : mi[2 * p + 1];
        }
        bool ge0 = mv[0] >= mv[1];
        float m = ge0 ? mv[0] : mv[1];
        int am = ge0 ? mi[0] : mi[1];

        float nfv = m + feat;
        fv = (lane < 16) ? nfv : NEG;
        if (lane < 16) bp_sm[t][lane] = (unsigned char)am;
    }
    __syncwarp();

    float best = -3.4e38f;
    int bt = 0;
#pragma unroll
    for (int s = 0; s < 16; s++) {
        float v = __shfl_sync(0xffffffffu, fv, s);
        float tv = v + trans[STOP_IDX * 16 + s];
        if (tv > best) { best = tv; bt = s; }
    }
    if (lane == 0) {
        out[b] = best;
        int tag = bt;
        for (int t = Tt - 1; t >= 0; t--) {
            out[64 + (size_t)t * Bb + b] = (float)tag;
            tag = bp_sm[t][tag];
        }
    }
}

// ---------------- launcher ----------------
// Launch order puts input_proj in ncu's sticky capture slot (#4) so this
// round's profile reports proj's real dur/regs/occ.
extern "C" void kernel_launch(void* const* d_in, const int* in_sizes, int n_in,
                              void* d_out, int out_size) {
    const int*   sentence = (const int*)d_in[0];
    const float* emb      = (const float*)d_in[1];
    const float* w_ih_f   = (const float*)d_in[2];
    const float* w_hh_f   = (const float*)d_in[3];
    const float* b_f      = (const float*)d_in[4];
    const float* w_ih_b   = (const float*)d_in[5];
    const float* w_hh_b   = (const float*)d_in[6];
    const float* b_b      = (const float*)d_in[7];
    const float* w_out    = (const float*)d_in[8];
    const float* b_out    = (const float*)d_in[9];
    const float* trans    = (const float*)d_in[10];
    float* out = (float*)d_out;
    (void)in_sizes; (void)n_in; (void)out_size;

    prep_whh_kernel<<<2048, 256>>>(w_hh_f, w_hh_b);
    dummy_kernel<<<1, 1>>>();
    dummy_kernel<<<1, 1>>>();
    dim3 pg(G4H / 128, (Tt * Bb) / 128, 2);
    input_proj_kernel<<<pg, 256>>>(sentence, emb, w_ih_f, b_f, w_ih_b, b_b);
    lstm_rec_kernel<<<128, 256>>>();
    feats_kernel<<<(Tt * Bb) / 8, 256>>>(w_out, b_out);
    viterbi_kernel<<<Bb, 32>>>(trans, out);
}

// round 17
// speedup vs baseline: 1.0049x; 1.0049x over previous
#include <cuda_runtime.h>
#include <cuda_bf16.h>
#include <math.h>
#include <stdint.h>

// Problem constants
#define Vv 50000
#define Ee 256
#define HD 512
#define Hh 256
#define Bb 64
#define Tt 512
#define Kk 16
#define G4H 1024
#define START_IDX 14
#define STOP_IDX 15
#define NEG (-10000.0f)

// ---------------- device scratch ----------------
__device__ __align__(16) float g_Wr2[2 * 1024 * 256];               // [d][col][k], col=j*4+gate
__device__ __align__(16) float g_Gpre[2ull * Tt * Bb * G4H];        // 268 MB
__device__ __align__(16) float g_hs[2ull * Tt * Bb * Hh];           // 67 MB
__device__ float g_feats[(size_t)Tt * Bb * Kk];

// ---------------- f32x2 helpers ----------------
__device__ __forceinline__ void ffma2(unsigned long long& d,
                                      unsigned long long a, unsigned long long b) {
    asm("fma.rn.f32x2 %0, %1, %2, %0;" : "+l"(d) : "l"(a), "l"(b));
}
__device__ __forceinline__ unsigned long long pack2(float x, float y) {
    unsigned long long r;
    asm("mov.b64 %0, {%1, %2};" : "=l"(r) : "f"(x), "f"(y));
    return r;
}
__device__ __forceinline__ float hadd2(unsigned long long v) {
    float lo = __uint_as_float((unsigned)(v & 0xffffffffull));
    float hi = __uint_as_float((unsigned)(v >> 32));
    return lo + hi;
}
__device__ __forceinline__ float fsig(float x) {
    return __fdividef(1.0f, 1.0f + __expf(-x));
}
__device__ __forceinline__ float ftanh(float x) {
    return __fdividef(2.0f, 1.0f + __expf(-2.0f * x)) - 1.0f;
}

// ---------------- cluster mbarrier helpers ----------------
__device__ __forceinline__ uint32_t smem_u32_of(const void* p) {
    uint32_t a;
    asm("{ .reg .u64 t0; cvta.to.shared.u64 t0, %1; cvt.u32.u64 %0, t0; }"
        : "=r"(a) : "l"(p));
    return a;
}
__device__ __forceinline__ void mbar_init(uint32_t mbar, uint32_t cnt) {
    asm volatile("mbarrier.init.shared.b64 [%0], %1;" :: "r"(mbar), "r"(cnt) : "memory");
}
__device__ __forceinline__ void mbar_arrive_expect(uint32_t mbar, uint32_t tx) {
    asm volatile("mbarrier.arrive.expect_tx.shared.b64 _, [%0], %1;"
                 :: "r"(mbar), "r"(tx) : "memory");
}
__device__ __forceinline__ void mbar_wait_cluster(uint32_t mbar, uint32_t parity) {
    asm volatile(
        "{\n\t"
        ".reg .pred P1;\n\t"
        "WAIT_%=:\n\t"
        "mbarrier.try_wait.parity.acquire.cta.shared::cta.b64 P1, [%0], %1, 0x989680;\n\t"
        "@P1 bra.uni DONE_%=;\n\t"
        "bra.uni WAIT_%=;\n\t"
        "DONE_%=:\n\t"
        "}"
        :: "r"(mbar), "r"(parity) : "memory");
}
__device__ __forceinline__ uint32_t mapa_u32(uint32_t addr, uint32_t rank) {
    uint32_t r;
    asm("mapa.shared::cluster.u32 %0, %1, %2;" : "=r"(r) : "r"(addr), "r"(rank));
    return r;
}
__device__ __forceinline__ void st_async_f64(uint32_t daddr, unsigned long long val,
                                             uint32_t mbar) {
    asm volatile(
        "st.async.weak.shared::cluster.mbarrier::complete_tx::bytes.b64 [%0], %1, [%2];"
        :: "r"(daddr), "l"(val), "r"(mbar) : "memory");
}

// ---------------- kernel 1: embedding gather + input projection SGEMM ----------------
// R17: R5 shape (256m x 128n, BK=8, 16m x 8n/thread, occ-1) with the B-side
// LDS de-conflicted: thread n-set = {tx*4..+3} U {64+tx*4..+3} -> B reads are
// two float4 at 16B lane stride (contiguous 256B, 0 conflicts, 2 wf) instead
// of stride-32B reads that were 4-way bank-conflicted. Bit-identical outputs
// (same per-output k-order and (m,m+1) pairing; only thread ownership moved).
// Extra grid x-slice (blockIdx.x==8) performs the w_hh reorder (prep fusion).
__global__ __launch_bounds__(256, 1) void input_proj_kernel(
    const int*   __restrict__ sentence,
    const float* __restrict__ emb,
    const float* __restrict__ wih_f, const float* __restrict__ bf,
    const float* __restrict__ wih_b, const float* __restrict__ bbias,
    const float* __restrict__ whh_f, const float* __restrict__ whh_b) {
    // ---- prep slice: reorder recurrent weights into g_Wr2 ----
    if (blockIdx.x == 8) {
        const int p = blockIdx.z * 128 + blockIdx.y;     // 0..255
        const int base = (p * 256 + threadIdx.x) * 8;
#pragma unroll
        for (int i = 0; i < 8; i++) {
            int idx = base + i;                          // over 2*1024*256
            int k = idx & 255;
            int col = (idx >> 8) & 1023;
            int dd = idx >> 18;
            int gate = col & 3;
            int j = col >> 2;
            const float* w = dd ? whh_b : whh_f;
            g_Wr2[idx] = w[(gate * 256 + j) * 256 + k];
        }
        return;
    }

    const int d = blockIdx.z;
    const float* wih = d ? wih_b : wih_f;
    const float* bias = d ? bbias : bf;

    __shared__ __align__(16) float As[2][8][256];    // 16 KB
    __shared__ __align__(16) float Bs[2][8][128];    // 8 KB

    const int tid = threadIdx.x;
    const int tx = tid & 15;          // n-group
    const int ty = tid >> 4;          // m-group
    const int m0 = blockIdx.y * 256;
    const int c0 = blockIdx.x * 128;

    // A loader: one m-row per thread
    const int mA = m0 + tid;
    const int tok = sentence[(mA & 63) * Tt + (mA >> 6)];
    const float* arow = emb + (size_t)tok * Ee;
    // B loader: row tid>>1, k-offset (tid&1)*4
    const int cB = c0 + (tid >> 1);
    const int rB = ((cB & 3) << 8) | (cB >> 2);
    const float* brow = wih + (size_t)rB * Ee + (tid & 1) * 4;

    unsigned long long acc2[8][8];
#pragma unroll
    for (int i = 0; i < 8; i++)
#pragma unroll
        for (int j = 0; j < 8; j++) acc2[i][j] = 0ull;

    // prologue: fill buffer 0
    {
        float4 a0 = *(const float4*)(arow + 0);
        float4 a1 = *(const float4*)(arow + 4);
        float4 bv = *(const float4*)(brow);
        float av[8] = {a0.x, a0.y, a0.z, a0.w, a1.x, a1.y, a1.z, a1.w};
#pragma unroll
        for (int i = 0; i < 8; i++) As[0][i][tid] = av[i];
        float bvv[4] = {bv.x, bv.y, bv.z, bv.w};
#pragma unroll
        for (int i = 0; i < 4; i++) Bs[0][(tid & 1) * 4 + i][tid >> 1] = bvv[i];
    }
    __syncthreads();

    for (int it = 0; it < 32; it++) {
        const int cur = it & 1;
        float4 a0n, a1n, bvn;
        if (it < 31) {
            a0n = *(const float4*)(arow + (it + 1) * 8);
            a1n = *(const float4*)(arow + (it + 1) * 8 + 4);
            bvn = *(const float4*)(brow + (it + 1) * 8);
        }
#pragma unroll
        for (int kk = 0; kk < 8; kk++) {
            const ulonglong2* pa = (const ulonglong2*)&As[cur][kk][ty * 16];
            ulonglong2 p0 = pa[0], p1 = pa[1], p2 = pa[2], p3 = pa[3];
            unsigned long long ra[8] = {p0.x, p0.y, p1.x, p1.y,
                                        p2.x, p2.y, p3.x, p3.y};
            // de-conflicted B reads: 16B lane stride, contiguous 256B halves
            float4 b0 = *(const float4*)&Bs[cur][kk][tx * 4];
            float4 b1 = *(const float4*)&Bs[cur][kk][64 + tx * 4];
            unsigned long long rb2[8];
            rb2[0] = pack2(b0.x, b0.x); rb2[1] = pack2(b0.y, b0.y);
            rb2[2] = pack2(b0.z, b0.z); rb2[3] = pack2(b0.w, b0.w);
            rb2[4] = pack2(b1.x, b1.x); rb2[5] = pack2(b1.y, b1.y);
            rb2[6] = pack2(b1.z, b1.z); rb2[7] = pack2(b1.w, b1.w);
#pragma unroll
            for (int mp = 0; mp < 8; mp++)
#pragma unroll
                for (int n = 0; n < 8; n++) ffma2(acc2[mp][n], ra[mp], rb2[n]);
        }
        if (it < 31) {
            const int nxt = cur ^ 1;
            float av[8] = {a0n.x, a0n.y, a0n.z, a0n.w, a1n.x, a1n.y, a1n.z, a1n.w};
#pragma unroll
            for (int i = 0; i < 8; i++) As[nxt][i][tid] = av[i];
            float bvv[4] = {bvn.x, bvn.y, bvn.z, bvn.w};
#pragma unroll
            for (int i = 0; i < 4; i++) Bs[nxt][(tid & 1) * 4 + i][tid >> 1] = bvv[i];
        }
        __syncthreads();
    }

    // bias per owned column: n 0..3 -> c0 + tx*4 + n; n 4..7 -> c0 + 64 + tx*4 + n-4
    float bsv[8];
#pragma unroll
    for (int n = 0; n < 8; n++) {
        int c = c0 + ((n < 4) ? (tx * 4 + n) : (64 + tx * 4 + (n - 4)));
        bsv[n] = bias[((c & 3) << 8) | (c >> 2)];
    }
#pragma unroll
    for (int mp = 0; mp < 8; mp++) {
        const int me = m0 + ty * 16 + 2 * mp;      // even m
        float oe[8], oo[8];
#pragma unroll
        for (int n = 0; n < 8; n++) {
            unsigned long long v = acc2[mp][n];
            oe[n] = __uint_as_float((unsigned)(v & 0xffffffffull)) + bsv[n];
            oo[n] = __uint_as_float((unsigned)(v >> 32)) + bsv[n];
        }
        {
            int t = me >> 6, b = me & 63;
            float* outp = g_Gpre + (((size_t)d * Tt + t) * Bb + b) * G4H + c0;
            *(float4*)(outp + tx * 4) = make_float4(oe[0], oe[1], oe[2], oe[3]);
            *(float4*)(outp + 64 + tx * 4) = make_float4(oe[4], oe[5], oe[6], oe[7]);
        }
        {
            int mo = me + 1;
            int t = mo >> 6, b = mo & 63;
            float* outp = g_Gpre + (((size_t)d * Tt + t) * Bb + b) * G4H + c0;
            *(float4*)(outp + tx * 4) = make_float4(oo[0], oo[1], oo[2], oo[3]);
            *(float4*)(outp + 64 + tx * 4) = make_float4(oo[4], oo[5], oo[6], oo[7]);
        }
    }
}

// ---------------- kernel 2: LSTM recurrence (R5 layout — proven best) ----------
// 128 CTAs, cluster 8. cid=blk>>3: d=cid>>3, batch group bg=cid&7 (8 batches).
// CTA rank r owns j in [r*32, r*32+32). Thread: jl=t>>3, kq=t&7 (k-split 8-way).
// Weights in registers. h pair-packed (shfl_xor 8) and broadcast via
// st.async.b64 from even-jl threads; per-step sync = tx-counted mbarrier.
// Gpre prefetch stays AFTER the GEMM (hoisting it spills at the 255-reg cap).
__global__ void __cluster_dims__(8, 1, 1) __launch_bounds__(256, 1) lstm_rec_kernel() {
    const int tidx = threadIdx.x;
    const int kq = tidx & 7;
    const int jl = tidx >> 3;
    const int cid = blockIdx.x >> 3;
    const int r = blockIdx.x & 7;
    const int d = cid >> 3;
    const int bg = cid & 7;
    const int b = bg * 8 + kq;
    const int jglob = r * 32 + jl;
    const int col0 = jglob * 4;

    __shared__ __align__(16) float h_sm[2][8][260];
    __shared__ __align__(8) unsigned long long mbars[2];

    // ---- weights into registers ----
    unsigned long long wu[4][16];
    const float* wbase = g_Wr2 + (size_t)d * 1024 * 256;
#pragma unroll
    for (int g = 0; g < 4; g++) {
        const ulonglong2* p = (const ulonglong2*)(wbase + (size_t)(col0 + g) * 256 + kq * 32);
#pragma unroll
        for (int q = 0; q < 8; q++) {
            ulonglong2 v = p[q];
            wu[g][2 * q + 0] = v.x;
            wu[g][2 * q + 1] = v.y;
        }
    }

    // zero step-0 buffer
    for (int i = tidx; i < 8 * 260; i += 256) ((float*)h_sm[0])[i] = 0.0f;
    float c = 0.0f;

    const uint32_t h_base = smem_u32_of(h_sm);
    const uint32_t mb_base = smem_u32_of(mbars);
    const uint32_t dmb = mb_base - h_base;

    if (tidx == 0) {
        mbar_init(mb_base, 1);
        mbar_init(mb_base + 8, 1);
        mbar_arrive_expect(mb_base, 8192);
        mbar_arrive_expect(mb_base + 8, 8192);
    }
    __syncthreads();
    asm volatile("barrier.cluster.arrive.aligned;" ::: "memory");
    asm volatile("barrier.cluster.wait.aligned;" ::: "memory");

    uint32_t ph[8];
#pragma unroll
    for (int rk = 0; rk < 8; rk++) ph[rk] = mapa_u32(h_base, rk);

    // pair store: even-jl thread writes (h_j, h_{j+1}) at float offset kq*260 + jglob
    const uint32_t hoff0 = (uint32_t)((kq * 260 + jglob) * 4);
    const uint32_t hoff1 = (uint32_t)(8 * 260 * 4) + hoff0;
    const bool sender = ((jl & 1) == 0);

    const int t0 = d ? (Tt - 1) : 0;
    const int tstep = d ? -1 : 1;
    const float4* gpre4 = (const float4*)g_Gpre;

    float4 g4 = gpre4[(((size_t)d * Tt + t0) * Bb + b) * 256 + jglob];

    for (int s = 0; s < Tt; s++) {
        const int t = t0 + s * tstep;
        const int cur = s & 1;

        if (s > 0) {
            uint32_t mb = mb_base + (uint32_t)(cur * 8);
            mbar_wait_cluster(mb, ((s - 1) >> 1) & 1);
            if (tidx == 0) mbar_arrive_expect(mb, 8192);   // re-arm for step s+2
        }

        // ---- GEMM: accf[g][slot], row = slot ^ kq ----
        float accf[4][8];
#pragma unroll
        for (int sl = 0; sl < 8; sl++) {
            unsigned long long a2[4] = {0ull, 0ull, 0ull, 0ull};
            const ulonglong2* hp = (const ulonglong2*)&h_sm[cur][sl ^ kq][kq * 32];
#pragma unroll
            for (int i = 0; i < 8; i++) {
                ulonglong2 h4 = hp[i];
                ffma2(a2[0], wu[0][2 * i], h4.x); ffma2(a2[0], wu[0][2 * i + 1], h4.y);
                ffma2(a2[1], wu[1][2 * i], h4.x); ffma2(a2[1], wu[1][2 * i + 1], h4.y);
                ffma2(a2[2], wu[2][2 * i], h4.x); ffma2(a2[2], wu[2][2 * i + 1], h4.y);
                ffma2(a2[3], wu[3][2 * i], h4.x); ffma2(a2[3], wu[3][2 * i + 1], h4.y);
            }
#pragma unroll
            for (int g = 0; g < 4; g++) accf[g][sl] = hadd2(a2[g]);
        }

        // prefetch next step's Gpre
        float4 g4n = g4;
        if (s + 1 < Tt) {
            const int tn = t + tstep;
            g4n = gpre4[(((size_t)d * Tt + tn) * Bb + b) * 256 + jglob];
        }

        // ---- reduce-scatter over kq lanes ----
#pragma unroll
        for (int g = 0; g < 4; g++) {
            accf[g][0] += __shfl_xor_sync(0xffffffffu, accf[g][4], 4);
            accf[g][1] += __shfl_xor_sync(0xffffffffu, accf[g][5], 4);
            accf[g][2] += __shfl_xor_sync(0xffffffffu, accf[g][6], 4);
            accf[g][3] += __shfl_xor_sync(0xffffffffu, accf[g][7], 4);
            accf[g][0] += __shfl_xor_sync(0xffffffffu, accf[g][2], 2);
            accf[g][1] += __shfl_xor_sync(0xffffffffu, accf[g][3], 2);
            accf[g][0] += __shfl_xor_sync(0xffffffffu, accf[g][1], 1);
        }

        // ---- LSTM cell ----
        float a0 = accf[0][0] + g4.x;
        float a1 = accf[1][0] + g4.y;
        float a2v = accf[2][0] + g4.z;
        float a3 = accf[3][0] + g4.w;
        float ig = fsig(a0), fg = fsig(a1), gv = ftanh(a2v), og = fsig(a3);
        c = fg * c + ig * gv;
        float h = og * ftanh(c);

        g_hs[(((size_t)d * Tt + t) * Bb + b) * Hh + jglob] = h;

        // pair h with jl-neighbor (lane ^ 8), even-jl threads send b64
        float hN = __shfl_xor_sync(0xffffffffu, h, 8);
        if (s + 1 < Tt && sender) {
            unsigned long long hv = pack2(h, hN);
            const uint32_t doff = (cur ^ 1) ? hoff1 : hoff0;
            const uint32_t moff = dmb + (uint32_t)((cur ^ 1) * 8);
#pragma unroll
            for (int rk = 0; rk < 8; rk++)
                st_async_f64(ph[rk] + doff, hv, ph[rk] + moff);
        }
        g4 = g4n;
    }
}

// ---------------- kernel 3: emission features ----------------
__global__ __launch_bounds__(256) void feats_kernel(const float* __restrict__ w_out,
                                                    const float* __restrict__ b_out) {
    const int lane = threadIdx.x & 31;
    const int warp = threadIdx.x >> 5;
    const int m = blockIdx.x * 8 + warp;
    const int t = m >> 6, b = m & 63;

    __shared__ float f_sm[8][16];

    float acc[16];
#pragma unroll
    for (int kk = 0; kk < 16; kk++) acc[kk] = 0.0f;

    const float* hf = g_hs + ((size_t)t * Bb + b) * Hh;
    const float* hb = g_hs + ((size_t)Tt * Bb * Hh) + ((size_t)t * Bb + b) * Hh;

#pragma unroll
    for (int i = 0; i < 16; i++) {
        int dd = i * 32 + lane;
        float hv = (dd < Hh) ? hf[dd] : hb[dd - Hh];
#pragma unroll
        for (int kk = 0; kk < 16; kk++) acc[kk] += hv * w_out[kk * HD + dd];
    }
#pragma unroll
    for (int kk = 0; kk < 16; kk++) {
        float s = acc[kk];
        s += __shfl_down_sync(0xffffffffu, s, 16);
        s += __shfl_down_sync(0xffffffffu, s, 8);
        s += __shfl_down_sync(0xffffffffu, s, 4);
        s += __shfl_down_sync(0xffffffffu, s, 2);
        s += __shfl_down_sync(0xffffffffu, s, 1);
        if (lane == 0) f_sm[warp][kk] = s;
    }
    __syncwarp();
    if (lane < 16)
        g_feats[((size_t)t * Bb + b) * Kk + lane] = f_sm[warp][lane] + b_out[lane];
}

// ---------------- kernel 4: Viterbi forward + backtrace (tree max/argmax) ------
__global__ __launch_bounds__(32) void viterbi_kernel(const float* __restrict__ trans,
                                                     float* __restrict__ out) {
    const int b = blockIdx.x;
    const int lane = threadIdx.x;

    __shared__ unsigned char bp_sm[Tt][16];

    float trans_r[16];
#pragma unroll
    for (int p = 0; p < 16; p++)
        trans_r[p] = (lane < 16) ? trans[lane * 16 + p] : 0.0f;

    float fv = (lane == START_IDX) ? 0.0f : NEG;
    if (lane >= 16) fv = NEG;

    float feat_n = (lane < 16) ? g_feats[((size_t)0 * Bb + b) * Kk + lane] : 0.0f;

    for (int t = 0; t < Tt; t++) {
        float feat = feat_n;
        if (t + 1 < Tt)
            feat_n = (lane < 16) ? g_feats[((size_t)(t + 1) * Bb + b) * Kk + lane] : 0.0f;

        float v[16];
#pragma unroll
        for (int p = 0; p < 16; p++)
            v[p] = __shfl_sync(0xffffffffu, fv, p) + trans_r[p];

        float mv[8]; int mi[8];
#pragma unroll
        for (int p = 0; p < 8; p++) {
            bool ge = v[2 * p] >= v[2 * p + 1];
            mv[p] = ge ? v[2 * p] : v[2 * p + 1];
            mi[p] = ge ? (2 * p) : (2 * p + 1);
        }
#pragma unroll
        for (int p = 0; p < 4; p++) {
            bool ge = mv[2 * p] >= mv[2 * p + 1];
            mv[p] = ge ? mv[2 * p] : mv[2 * p + 1];
            mi[p] = ge ? mi[2 * p] : mi[2 * p + 1];
        }
#pragma unroll
        for (int p = 0; p < 2; p++) {
            bool ge = mv[2 * p] >= mv[2 * p + 1];
            mv[p] = ge ? mv[2 * p] : mv[2 * p + 1];
            mi[p] = ge ? mi[2 * p] : mi[2 * p + 1];
        }
        bool ge0 = mv[0] >= mv[1];
        float m = ge0 ? mv[0] : mv[1];
        int am = ge0 ? mi[0] : mi[1];

        float nfv = m + feat;
        fv = (lane < 16) ? nfv : NEG;
        if (lane < 16) bp_sm[t][lane] = (unsigned char)am;
    }
    __syncwarp();

    float best = -3.4e38f;
    int bt = 0;
#pragma unroll
    for (int s = 0; s < 16; s++) {
        float v = __shfl_sync(0xffffffffu, fv, s);
        float tv = v + trans[STOP_IDX * 16 + s];
        if (tv > best) { best = tv; bt = s; }
    }
    if (lane == 0) {
        out[b] = best;
        int tag = bt;
        for (int t = Tt - 1; t >= 0; t--) {
            out[64 + (size_t)t * Bb + b] = (float)tag;
            tag = bp_sm[t][tag];
        }
    }
}

// ---------------- launcher ----------------
// 4 launches total: proj (with fused w_hh reorder slice), lstm, feats, viterbi.
extern "C" void kernel_launch(void* const* d_in, const int* in_sizes, int n_in,
                              void* d_out, int out_size) {
    const int*   sentence = (const int*)d_in[0];
    const float* emb      = (const float*)d_in[1];
    const float* w_ih_f   = (const float*)d_in[2];
    const float* w_hh_f   = (const float*)d_in[3];
    const float* b_f      = (const float*)d_in[4];
    const float* w_ih_b   = (const float*)d_in[5];
    const float* w_hh_b   = (const float*)d_in[6];
    const float* b_b      = (const float*)d_in[7];
    const float* w_out    = (const float*)d_in[8];
    const float* b_out    = (const float*)d_in[9];
    const float* trans    = (const float*)d_in[10];
    float* out = (float*)d_out;
    (void)in_sizes; (void)n_in; (void)out_size;

    dim3 pg(G4H / 128 + 1, (Tt * Bb) / 256, 2);   // x==8 slice = w_hh reorder
    input_proj_kernel<<<pg, 256>>>(sentence, emb, w_ih_f, b_f, w_ih_b, b_b,
                                   w_hh_f, w_hh_b);
    lstm_rec_kernel<<<128, 256>>>();
    feats_kernel<<<(Tt * Bb) / 8, 256>>>(w_out, b_out);
    viterbi_kernel<<<Bb, 32>>>(trans, out);
}